// round 1
// baseline (speedup 1.0000x reference)
#include <cuda_runtime.h>

#define NN 10000
#define NE 80000

__device__ __constant__ int c_EXPAND[9] = {0,1,1,1,2,2,2,2,2};

// ---------------- scratch (static device arrays; no allocation) ----------------
__device__ float g_xn  [NN*576];    // enorm(x)
__device__ float g_rad [NE*384];    // radial features (E,3,128)
__device__ float g_val0[NE*128];    // silu(g_scalar)
__device__ float g_gdir[NE*256];    // sigmoid dir gates (E,2,128)
__device__ float g_gten[NE*256];    // sigmoid ten gates (E,2,128)
__device__ float g_e   [NE*8];      // exp(logits)
__device__ float g_num [NN*1152];   // attn-weighted message numerator
__device__ float g_den [NN*8];      // attn denominator
__device__ float g_x1  [NN*576];    // x after first residual
__device__ float g_yn  [NN*576];    // enorm(x1)
__device__ float g_gsil[NN*128];    // silu(gate)
__device__ float g_gsig[NN*128];    // sigmoid(gate)

__device__ __forceinline__ float sigm(float z) { return 1.f / (1.f + __expf(-z)); }

// ---------------- zero accumulators ----------------
__global__ void zero_kernel() {
    int i = blockIdx.x * blockDim.x + threadIdx.x;
    if (i < NN*1152) g_num[i] = 0.f;
    if (i < NN*8)    g_den[i] = 0.f;
}

// ---------------- equivariant norm: dst = enorm(src) ----------------
__global__ void enorm_kernel(const float* __restrict__ src, float* __restrict__ dst) {
    int n = blockIdx.x, c = threadIdx.x;   // 64 threads
    const float* p = src + n*576 + c;
    float v[9];
#pragma unroll
    for (int k = 0; k < 9; k++) v[k] = p[k*64];
    float s0 = v[0]*v[0];
    float s1 = v[1]*v[1] + v[2]*v[2] + v[3]*v[3];
    float s2 = v[4]*v[4] + v[5]*v[5] + v[6]*v[6] + v[7]*v[7] + v[8]*v[8];
#pragma unroll
    for (int off = 16; off; off >>= 1) {
        s0 += __shfl_xor_sync(0xffffffffu, s0, off);
        s1 += __shfl_xor_sync(0xffffffffu, s1, off);
        s2 += __shfl_xor_sync(0xffffffffu, s2, off);
    }
    __shared__ float red[3][2];
    if ((c & 31) == 0) { red[0][c>>5] = s0; red[1][c>>5] = s1; red[2][c>>5] = s2; }
    __syncthreads();
    float t0 = red[0][0] + red[0][1];
    float t1 = red[1][0] + red[1][1];
    float t2 = red[2][0] + red[2][1];
    float sc0 = rsqrtf(t0 * (1.f/64.f)  + 1e-6f);
    float sc1 = rsqrtf(t1 * (1.f/192.f) + 1e-6f);
    float sc2 = rsqrtf(t2 * (1.f/320.f) + 1e-6f);
    float* q = dst + n*576 + c;
    q[0] = v[0]*sc0;
#pragma unroll
    for (int k = 1; k < 4; k++) q[k*64] = v[k]*sc1;
#pragma unroll
    for (int k = 4; k < 9; k++) q[k*64] = v[k]*sc2;
}

// ---------------- radial MLP: rad = silu(ef@W1+b1)@W2+b2 ----------------
__global__ void __launch_bounds__(128) rad_kernel(
    const float* __restrict__ edist, const float* __restrict__ semb,
    const float* __restrict__ temb,  const float* __restrict__ W1,
    const float* __restrict__ b1,    const float* __restrict__ W2,
    const float* __restrict__ b2,    const int* __restrict__ anum,
    const int* __restrict__ eidx)
{
    __shared__ float ef[128][20];   // [c][e], 16 edges + pad
    __shared__ float h1[128][20];
    __shared__ int zsrc[16], ztgt[16];
    int e0 = blockIdx.x * 16, t = threadIdx.x;
    if (t < 16)       zsrc[t]    = anum[eidx[e0 + t]];
    else if (t < 32)  ztgt[t-16] = anum[eidx[NE + e0 + t - 16]];
    __syncthreads();
#pragma unroll
    for (int e = 0; e < 16; e++) {
        float v;
        if (t < 64)      v = edist[(e0+e)*64 + t];
        else if (t < 96) v = semb[zsrc[e]*32 + (t-64)];
        else             v = temb[ztgt[e]*32 + (t-96)];
        ef[t][e] = v;
    }
    __syncthreads();
    {
        float acc[16];
#pragma unroll
        for (int e = 0; e < 16; e++) acc[e] = 0.f;
        const float* W = W1 + t;
#pragma unroll 4
        for (int c = 0; c < 128; c++) {
            float w = W[c*128];
            const float4* xr = (const float4*)&ef[c][0];
#pragma unroll
            for (int e4 = 0; e4 < 4; e4++) {
                float4 xv = xr[e4];
                acc[e4*4+0] += w*xv.x; acc[e4*4+1] += w*xv.y;
                acc[e4*4+2] += w*xv.z; acc[e4*4+3] += w*xv.w;
            }
        }
        float bb = b1[t];
#pragma unroll
        for (int e = 0; e < 16; e++) { float z = acc[e] + bb; h1[t][e] = z * sigm(z); }
    }
    __syncthreads();
    for (int j = 0; j < 3; j++) {
        int o = j*128 + t;
        float acc[16];
#pragma unroll
        for (int e = 0; e < 16; e++) acc[e] = 0.f;
        const float* W = W2 + o;
#pragma unroll 4
        for (int c = 0; c < 128; c++) {
            float w = W[c*384];
            const float4* xr = (const float4*)&h1[c][0];
#pragma unroll
            for (int e4 = 0; e4 < 4; e4++) {
                float4 xv = xr[e4];
                acc[e4*4+0] += w*xv.x; acc[e4*4+1] += w*xv.y;
                acc[e4*4+2] += w*xv.z; acc[e4*4+3] += w*xv.w;
            }
        }
        float bb = b2[o];
#pragma unroll
        for (int e = 0; e < 16; e++) g_rad[(e0+e)*384 + o] = acc[e] + bb;
    }
}

// ---------------- extra = x_edge[:,0]@W_m0 ; gates / val0 / attention logits ----------------
__global__ void __launch_bounds__(128) extra_kernel(
    const float* __restrict__ Wm0, const float* __restrict__ lng,
    const float* __restrict__ lnb, const float* __restrict__ adot,
    const int* __restrict__ eidx)
{
    __shared__ float xe0[128][20];
    __shared__ float chunk[16][128];
    __shared__ int src_s[16], tgt_s[16];
    int e0 = blockIdx.x * 16, t = threadIdx.x;
    if (t < 16)      src_s[t]    = eidx[e0 + t];
    else if (t < 32) tgt_s[t-16] = eidx[NE + e0 + t - 16];
    __syncthreads();
#pragma unroll
    for (int e = 0; e < 16; e++) {
        float xv = (t < 64) ? g_xn[src_s[e]*576 + t] : g_xn[tgt_s[e]*576 + (t-64)];
        xe0[t][e] = xv * g_rad[(e0+e)*384 + t];   // deg-0 radial block
    }
    __syncthreads();
    for (int oc = 0; oc < 7; oc++) {
        float acc[16];
#pragma unroll
        for (int e = 0; e < 16; e++) acc[e] = 0.f;
        const float* W = Wm0 + oc*128 + t;
#pragma unroll 4
        for (int c = 0; c < 128; c++) {
            float w = W[c*896];
            const float4* xr = (const float4*)&xe0[c][0];
#pragma unroll
            for (int e4 = 0; e4 < 4; e4++) {
                float4 xv = xr[e4];
                acc[e4*4+0] += w*xv.x; acc[e4*4+1] += w*xv.y;
                acc[e4*4+2] += w*xv.z; acc[e4*4+3] += w*xv.w;
            }
        }
        if (oc < 2) {                       // alpha_f chunk: heads 4*oc .. 4*oc+3
#pragma unroll
            for (int e = 0; e < 16; e++) chunk[e][t] = acc[e];
            __syncthreads();
            if (t < 64) {
                int e = t >> 2, h4 = t & 3, h = oc*4 + h4;
                const float* ap = &chunk[e][h4*32];
                float m = 0.f, m2 = 0.f;
#pragma unroll
                for (int a = 0; a < 32; a++) { float v = ap[a]; m += v; m2 += v*v; }
                m *= (1.f/32.f);
                float var = m2*(1.f/32.f) - m*m;
                float rs = rsqrtf(var + 1e-5f);
                float logit = 0.f;
#pragma unroll
                for (int a = 0; a < 32; a++) {
                    float an = (ap[a] - m)*rs*lng[a] + lnb[a];
                    float sl = 0.2f*an + 0.8f*an*sigm(an);
                    logit += sl * adot[h*32 + a];
                }
                float ee = __expf(logit);
                g_e[(e0+e)*8 + h] = ee;
                atomicAdd(&g_den[tgt_s[e]*8 + h], ee);
            }
            __syncthreads();
        } else if (oc == 2) {               // g_scalar -> silu
#pragma unroll
            for (int e = 0; e < 16; e++) { float z = acc[e]; g_val0[(e0+e)*128 + t] = z * sigm(z); }
        } else {                            // gates: oc=3,4 -> dir(l=0,1); oc=5,6 -> ten(l=0,1)
            int which = oc - 3;
#pragma unroll
            for (int e = 0; e < 16; e++) {
                float s = sigm(acc[e]);
                if (which < 2) g_gdir[(e0+e)*256 + which*128 + t] = s;
                else           g_gten[(e0+e)*256 + (which-2)*128 + t] = s;
            }
        }
    }
}

// ---------------- fused conv1 + gating + conv2 + attention scatter ----------------
__global__ void __launch_bounds__(128) edge_main_kernel(
    const float* __restrict__ Wc1, const float* __restrict__ Wxj,
    const float* __restrict__ Wc2, const float* __restrict__ rl,
    const int* __restrict__ eidx)
{
    __shared__ float bufA[128][36];   // x_edge tile, later val tile  [c][e]
    __shared__ float xsb [64][36];    // xs tile (for xj_proj)
    __shared__ float rl_s[32][8];
    __shared__ float ee_s[32][8];
    __shared__ int src_s[32], tgt_s[32];
    int e0 = blockIdx.x * 32, t = threadIdx.x;
    if (t < 32)      src_s[t]    = eidx[e0 + t];
    else if (t < 64) tgt_s[t-32] = eidx[NE + e0 + t - 32];
    for (int i = t; i < 256; i += 128) { int e = i>>3, j = i&7; rl_s[e][j] = rl[(e0+e)*8 + j]; }
    for (int i = t; i < 256; i += 128) { int e = i>>3, j = i&7; ee_s[e][j] = g_e[(e0+e)*8 + j]; }
    __syncthreads();

    for (int k = 0; k < 9; k++) {
        int deg = (k == 0) ? 0 : ((k < 4) ? 1 : 2);
        if (k == 0) {
#pragma unroll
            for (int e = 0; e < 32; e++) bufA[t][e] = g_val0[(e0+e)*128 + t];
            __syncthreads();
        } else {
#pragma unroll
            for (int e = 0; e < 32; e++) {
                float rv = g_rad[(e0+e)*384 + deg*128 + t];
                float xv;
                if (t < 64) { xv = g_xn[src_s[e]*576 + k*64 + t];        xsb[t][e] = xv; }
                else        { xv = g_xn[tgt_s[e]*576 + k*64 + (t-64)]; }
                bufA[t][e] = xv * rv;
            }
            __syncthreads();
            float acc1[32], acc2[32];
#pragma unroll
            for (int e = 0; e < 32; e++) { acc1[e] = 0.f; acc2[e] = 0.f; }
            const float* W = Wc1 + deg*16384 + t;
#pragma unroll 4
            for (int c = 0; c < 128; c++) {
                float w = W[c*128];
                const float4* xr = (const float4*)&bufA[c][0];
#pragma unroll
                for (int e4 = 0; e4 < 8; e4++) {
                    float4 xv = xr[e4];
                    acc1[e4*4+0] += w*xv.x; acc1[e4*4+1] += w*xv.y;
                    acc1[e4*4+2] += w*xv.z; acc1[e4*4+3] += w*xv.w;
                }
            }
            const float* W2 = Wxj + t;
#pragma unroll 2
            for (int c = 0; c < 64; c++) {
                float w = W2[c*128];
                const float4* xr = (const float4*)&xsb[c][0];
#pragma unroll
                for (int e4 = 0; e4 < 8; e4++) {
                    float4 xv = xr[e4];
                    acc2[e4*4+0] += w*xv.x; acc2[e4*4+1] += w*xv.y;
                    acc2[e4*4+2] += w*xv.z; acc2[e4*4+3] += w*xv.w;
                }
            }
            __syncthreads();   // done reading bufA/xsb
            int l = (k < 4) ? 0 : 1;   // EXP1[k-1]
            int base = e0*256 + l*128 + t;
#pragma unroll
            for (int e = 0; e < 32; e++) {
                float gd = g_gdir[base + e*256];
                float gt = g_gten[base + e*256];
                bufA[t][e] = acc1[e] + rl_s[e][k-1]*gd + acc2[e]*gt;   // val
            }
            __syncthreads();
        }
        // conv2 + attention-weighted scatter
        float acc3[32];
#pragma unroll
        for (int e = 0; e < 32; e++) acc3[e] = 0.f;
        const float* W3 = Wc2 + deg*16384 + t;
#pragma unroll 4
        for (int d = 0; d < 128; d++) {
            float w = W3[d*128];
            const float4* xr = (const float4*)&bufA[d][0];
#pragma unroll
            for (int e4 = 0; e4 < 8; e4++) {
                float4 xv = xr[e4];
                acc3[e4*4+0] += w*xv.x; acc3[e4*4+1] += w*xv.y;
                acc3[e4*4+2] += w*xv.z; acc3[e4*4+3] += w*xv.w;
            }
        }
        int h = t >> 4;
#pragma unroll
        for (int e = 0; e < 32; e++)
            atomicAdd(&g_num[tgt_s[e]*1152 + k*128 + t], acc3[e]*ee_s[e][h]);
        __syncthreads();
    }
}

// ---------------- node: x1 = x + so3_linear(node_out, W_proj, b_proj) ----------------
__global__ void __launch_bounds__(128) proj_kernel(
    const float* __restrict__ x, const float* __restrict__ Wp, const float* __restrict__ bp)
{
    int n = blockIdx.x, t = threadIdx.x;
    __shared__ float no_s[1152];
    __shared__ float den_s[8];
    if (t < 8) den_s[t] = g_den[n*8 + t] + 1e-30f;
    __syncthreads();
    for (int i = t; i < 1152; i += 128) {
        int o = i & 127;
        no_s[i] = g_num[n*1152 + i] / den_s[o >> 4];
    }
    __syncthreads();
    for (int idx = t; idx < 576; idx += 128) {
        int k = idx >> 6, d = idx & 63;
        int deg = c_EXPAND[k];
        float acc = (k == 0) ? bp[d] : 0.f;
        const float* W = Wp + deg*8192 + d;
        const float* v = &no_s[k*128];
#pragma unroll 4
        for (int c = 0; c < 128; c++) acc += v[c] * W[c*64];
        g_x1[n*576 + idx] = x[n*576 + idx] + acc;
    }
}

// ---------------- node: gate = yn[:,0]@W_gate + b_gate ----------------
__global__ void __launch_bounds__(128) gate_kernel(
    const float* __restrict__ Wg, const float* __restrict__ bg)
{
    int n = blockIdx.x, t = threadIdx.x;
    __shared__ float y0[64];
    if (t < 64) y0[t] = g_yn[n*576 + t];
    __syncthreads();
    float acc = bg[t];
    const float* W = Wg + t;
#pragma unroll 4
    for (int c = 0; c < 64; c++) acc += y0[c] * W[c*128];
    g_gsil[n*128 + t] = acc * sigm(acc);
    g_gsig[n*128 + t] = sigm(acc);
}

// ---------------- node: FFN + second residual -> output ----------------
__global__ void __launch_bounds__(128) ffn_kernel(
    const float* __restrict__ Wf1, const float* __restrict__ Wf2,
    const float* __restrict__ bf2, float* __restrict__ out)
{
    int n = blockIdx.x, t = threadIdx.x;
    __shared__ float yn_s[576];
    __shared__ float h_s[1152];
    for (int i = t; i < 576; i += 128) yn_s[i] = g_yn[n*576 + i];
    __syncthreads();
    float gs = g_gsig[n*128 + t];
#pragma unroll
    for (int k = 1; k < 9; k++) {
        int deg = (k < 4) ? 1 : 2;
        float acc = 0.f;
        const float* W = Wf1 + deg*8192 + t;
        const float* v = &yn_s[k*64];
#pragma unroll 4
        for (int c = 0; c < 64; c++) acc += v[c] * W[c*128];
        h_s[k*128 + t] = acc * gs;
    }
    h_s[t] = g_gsil[n*128 + t];
    __syncthreads();
    for (int idx = t; idx < 576; idx += 128) {
        int k = idx >> 6, d = idx & 63;
        int deg = c_EXPAND[k];
        float acc = (k == 0) ? bf2[d] : 0.f;
        const float* W = Wf2 + deg*8192 + d;
        const float* v = &h_s[k*128];
#pragma unroll 4
        for (int c = 0; c < 128; c++) acc += v[c] * W[c*64];
        out[n*576 + idx] = g_x1[n*576 + idx] + acc;
    }
}

// ---------------- launch ----------------
extern "C" void kernel_launch(void* const* d_in, const int* in_sizes, int n_in,
                              void* d_out, int out_size)
{
    const float* x     = (const float*)d_in[0];
    const float* edist = (const float*)d_in[1];
    const float* rl    = (const float*)d_in[2];
    const float* semb  = (const float*)d_in[3];
    const float* temb  = (const float*)d_in[4];
    const float* W1    = (const float*)d_in[5];
    const float* b1    = (const float*)d_in[6];
    const float* W2    = (const float*)d_in[7];
    const float* b2    = (const float*)d_in[8];
    const float* Wc1   = (const float*)d_in[9];
    const float* Wm0   = (const float*)d_in[10];
    const float* lng   = (const float*)d_in[11];
    const float* lnb   = (const float*)d_in[12];
    const float* adot  = (const float*)d_in[13];
    const float* Wxj   = (const float*)d_in[14];
    const float* Wc2   = (const float*)d_in[15];
    const float* Wp    = (const float*)d_in[16];
    const float* bp    = (const float*)d_in[17];
    const float* Wg    = (const float*)d_in[18];
    const float* bg    = (const float*)d_in[19];
    const float* Wf1   = (const float*)d_in[20];
    /* b_ffn1 (d_in[21]) is only added at k=0, whose slot is replaced by silu(g) -> unused */
    const float* Wf2   = (const float*)d_in[22];
    const float* bf2   = (const float*)d_in[23];
    const int*   anum  = (const int*)d_in[24];
    const int*   eidx  = (const int*)d_in[25];
    float* out = (float*)d_out;

    float *p_xn, *p_x1, *p_yn;
    cudaGetSymbolAddress((void**)&p_xn, g_xn);
    cudaGetSymbolAddress((void**)&p_x1, g_x1);
    cudaGetSymbolAddress((void**)&p_yn, g_yn);

    zero_kernel<<<(NN*1152 + 255)/256, 256>>>();
    enorm_kernel<<<NN, 64>>>(x, p_xn);
    rad_kernel<<<NE/16, 128>>>(edist, semb, temb, W1, b1, W2, b2, anum, eidx);
    extra_kernel<<<NE/16, 128>>>(Wm0, lng, lnb, adot, eidx);
    edge_main_kernel<<<NE/32, 128>>>(Wc1, Wxj, Wc2, rl, eidx);
    proj_kernel<<<NN, 128>>>(x, Wp, bp);
    enorm_kernel<<<NN, 64>>>(p_x1, p_yn);
    gate_kernel<<<NN, 128>>>(Wg, bg);
    ffn_kernel<<<NN, 128>>>(Wf1, Wf2, bf2, out);
}